// round 3
// baseline (speedup 1.0000x reference)
#include <cuda_runtime.h>

#define T_ 2048
#define B_ 256
#define M_ 32
#define HALF_ 16
#define KPOLY 4
#define PF 4

__device__ float g_nllh[B_];
__device__ int g_done;

__device__ __forceinline__ float ex2f_(float x) {
    float y; asm("ex2.approx.ftz.f32 %0, %1;" : "=f"(y) : "f"(x)); return y;
}
__device__ __forceinline__ float lg2f_(float x) {
    float y; asm("lg2.approx.ftz.f32 %0, %1;" : "=f"(y) : "f"(x)); return y;
}
__device__ __forceinline__ float rcpf_(float x) {
    float y; asm("rcp.approx.ftz.f32 %0, %1;" : "=f"(y) : "f"(x)); return y;
}

// e^x via degree-7 Taylor (|x| <= ~1.2 here; rel err ~3e-5)
__device__ __forceinline__ float poly_exp(float x) {
    float e = fmaf(x, 1.9841270e-4f, 1.3888889e-3f);
    e = fmaf(x, e, 8.3333333e-3f);
    e = fmaf(x, e, 4.1666668e-2f);
    e = fmaf(x, e, 1.6666667e-1f);
    e = fmaf(x, e, 0.5f);
    e = fmaf(x, e, 1.0f);
    e = fmaf(x, e, 1.0f);
    return e;
}

__global__ __launch_bounds__(128, 1)
void crf_kernel(const float* __restrict__ em,     // [T,B,M]
                const int*   __restrict__ tags,   // [T,B]
                const float* __restrict__ wt,     // [T,B]
                const int*   __restrict__ mk,     // [T,B]
                const float* __restrict__ trans,  // [M,M]
                const float* __restrict__ startt, // [M]
                const float* __restrict__ endt,   // [M]
                float* __restrict__ out)
{
    const int lane = threadIdx.x & 31;
    const int warp = threadIdx.x >> 5;
    const int pair = warp >> 1;   // which batch within CTA
    const int half = warp & 1;    // which half of transition rows
    const int b = blockIdx.x * 2 + pair;
    const int i0 = half * HALF_;
    const unsigned FULL = 0xffffffffu;
    const float L2E = 1.4426950408889634f;
    const float LN2 = 0.6931471805599453f;

    __shared__ float xch[2][2][2][M_];  // [buf][pair][half][lane]
    __shared__ float s_sc[2][2];
    __shared__ int   s_cnt[2][2];
    __shared__ int   s_last;

    // lane j holds trans[i0+k][j]; poly rows keep natural log, mufu rows pre-scaled by log2(e)
    float tc[HALF_];
#pragma unroll
    for (int k = 0; k < HALF_; ++k) {
        float tv = trans[(i0 + k) * M_ + lane];
        tc[k] = (k < KPOLY) ? tv : tv * L2E;
    }

    // alpha0 = start + emissions[0]; p = exp(alpha0 - M_1), M_1 = alpha0[lane0]
    float alpha0 = startt[lane] + em[(size_t)b * M_ + lane];
    float a0 = __shfl_sync(FULL, alpha0, 0);
    float mC = a0, mN = a0;                 // M_t, M_{t+1}
    float p = ex2f_((alpha0 - a0) * L2E);

    // e[k] for step 1 (uses wt[0])
    float e[HALF_];
    {
        const float invw = rcpf_(wt[b]);
#pragma unroll
        for (int k = 0; k < HALF_; ++k)
            e[k] = (k < KPOLY) ? poly_exp(tc[k] * invw) : ex2f_(tc[k] * invw);
    }

    // prefetch ring: slot (u-1)&3 holds step u data (em[u], wt[u-1], mk[u])
    float emb[PF], wb[PF]; int mkb[PF];
#pragma unroll
    for (int j = 0; j < PF; ++j) {
        const int t = 1 + j;
        emb[j] = em[((size_t)t * B_ + b) * M_ + lane];
        wb[j]  = wt[(t - 1) * B_ + b];
        mkb[j] = mk[t * B_ + b];
    }

    int buf = 0;
#pragma unroll 4
    for (int t = 1; t < T_; ++t) {
        const int idx = (t - 1) & (PF - 1);
        const float em_c = emb[idx];
        const int   mk_c = mkb[idx];
        const float w_next = wb[t & (PF - 1)];   // wt[t] = w for step t+1
        const int tp = t + PF;
        if (tp < T_) {
            emb[idx] = em[((size_t)tp * B_ + b) * M_ + lane];
            wb[idx]  = wt[(tp - 1) * B_ + b];
            mkb[idx] = mk[tp * B_ + b];
        }

        // ---- critical path: exp-domain mat-vec using precomputed e ----
        float c0 = 0.f, c1 = 0.f, c2 = 0.f, c3 = 0.f;
#pragma unroll
        for (int k = 0; k < HALF_; ++k) {
            const float pk = __shfl_sync(FULL, p, i0 + k);
            if ((k & 3) == 0)      c0 = fmaf(pk, e[k], c0);
            else if ((k & 3) == 1) c1 = fmaf(pk, e[k], c1);
            else if ((k & 3) == 2) c2 = fmaf(pk, e[k], c2);
            else                   c3 = fmaf(pk, e[k], c3);
        }
        const float sh = (c0 + c1) + (c2 + c3);
        xch[buf][pair][half][lane] = sh;

        // ---- shadow work (independent of s): q, next-step e, alpha0 base ----
        const float invw = rcpf_(w_next);
        const float dm = (mC - mN) * L2E;
        const float q = ex2f_(fmaf(em_c, L2E, dm));   // exp(em_t + M_t - M_{t+1})
        const float em0 = __shfl_sync(FULL, em_c, 0);
        const float base0 = em0 + mC;
#pragma unroll
        for (int k = 0; k < HALF_; ++k)
            e[k] = (k < KPOLY) ? poly_exp(tc[k] * invw) : ex2f_(tc[k] * invw);

        __syncthreads();
        const float s = sh + xch[buf][pair][half ^ 1][lane];
        buf ^= 1;

        // ---- short tail: p' = s*q (masked step: p' = p * exp(M_t - M_{t+1})) ----
        const float s0 = __shfl_sync(FULL, s, 0);
        if (mk_c) {
            p = s * q;
            a0 = fmaf(lg2f_(s0), LN2, base0);   // alpha_t[lane0], off critical path
        } else {
            p = p * ex2f_(dm);
        }
        mC = mN; mN = a0;
    }

    // alpha_{T-1} = ln(p) + M_T ;  log_Z = logsumexp(alpha + end_transitions)
    float logZ;
    {
        const float alphaf = fmaf(lg2f_(p), LN2, mC);
        float v = alphaf + endt[lane];
        float mz = v;
#pragma unroll
        for (int off = 16; off; off >>= 1)
            mz = fmaxf(mz, __shfl_xor_sync(FULL, mz, off));
        float ez = ex2f_((v - mz) * L2E);
#pragma unroll
        for (int off = 16; off; off >>= 1)
            ez += __shfl_xor_sync(FULL, ez, off);
        logZ = fmaf(lg2f_(ez), LN2, mz);
    }

    // ---- gold-path score: each warp covers its half of the T range ----
    float sc = 0.f; int cnt = 0;
    const int tbeg = half * (T_ / 2);
#pragma unroll 2
    for (int base = tbeg; base < tbeg + T_ / 2; base += 32) {
        const int t = base + lane;
        const int m_t = mk[t * B_ + b];
        cnt += m_t;
        if (m_t) {
            const int tg = tags[t * B_ + b];
            sc += em[((size_t)t * B_ + b) * M_ + tg];
            if (t > 0) {
                const int mp = mk[(t - 1) * B_ + b];
                const int tgp = mp ? tags[(t - 1) * B_ + b] : 1;
                sc += trans[tgp * M_ + tg] * rcpf_(wt[(t - 1) * B_ + b]);
            }
        }
    }
#pragma unroll
    for (int off = 16; off; off >>= 1) {
        sc  += __shfl_xor_sync(FULL, sc, off);
        cnt += __shfl_xor_sync(FULL, cnt, off);
    }
    if (lane == 0) { s_sc[pair][half] = sc; s_cnt[pair][half] = cnt; }
    __syncthreads();
    if (half == 0 && lane == 0) {
        float st = s_sc[pair][0] + s_sc[pair][1];
        const int cn = s_cnt[pair][0] + s_cnt[pair][1];
        st += startt[tags[b]] + endt[tags[(size_t)(cn - 1) * B_ + b]];
        g_nllh[b] = logZ - st;
    }

    // ---- last-block folds the deterministic final reduction ----
    __threadfence();
    __syncthreads();
    if (threadIdx.x == 0)
        s_last = (atomicAdd(&g_done, 1) == (int)gridDim.x - 1) ? 1 : 0;
    __syncthreads();
    if (s_last && warp == 0) {
        float v = 0.f;
#pragma unroll
        for (int k = 0; k < B_ / 32; ++k) {
            float x;
            asm volatile("ld.global.cg.f32 %0, [%1];" : "=f"(x) : "l"(g_nllh + k * 32 + lane));
            v += x;
        }
#pragma unroll
        for (int off = 16; off; off >>= 1)
            v += __shfl_xor_sync(FULL, v, off);
        if (lane == 0) { out[0] = v; g_done = 0; }
    }
}

extern "C" void kernel_launch(void* const* d_in, const int* in_sizes, int n_in,
                              void* d_out, int out_size)
{
    const float* em     = (const float*)d_in[0];
    const int*   tags   = (const int*)  d_in[1];
    const float* wt     = (const float*)d_in[2];
    const int*   mask   = (const int*)  d_in[3];
    const float* trans  = (const float*)d_in[4];
    const float* startt = (const float*)d_in[5];
    const float* endt   = (const float*)d_in[6];

    crf_kernel<<<B_ / 2, 128>>>(em, tags, wt, mask, trans, startt, endt, (float*)d_out);
}